// round 3
// baseline (speedup 1.0000x reference)
#include <cuda_runtime.h>

// Problem constants
#define B      32
#define T_IN   24
#define T_OUT  12
#define D      10
#define M      64
#define N      128
#define MN     (M * N)                 // 8192
#define IN_T_STRIDE  (D * MN)          // 81920 floats between t slices
#define IN_B_STRIDE  (T_IN * IN_T_STRIDE)
#define OUT_B_STRIDE (T_OUT * MN)
#define MU_    0.08f                   // 2/(T_IN+1)
#define LAM    0.92f                   // 1 - MU

__global__ __launch_bounds__(256)
void movavg_kernel(const float* __restrict__ x, float* __restrict__ out)
{
    const int tid = blockIdx.x * 256 + threadIdx.x;  // over B*MN = 262144
    const int b   = tid >> 13;                       // / 8192
    const int mn  = tid & (MN - 1);

    const float* __restrict__ xin = x + b * IN_B_STRIDE + mn;

    // Compile-time constants: lam23 = LAM^23, base = lam23/24, Kc = MU*lam23
    float lam23 = 1.0f;
    #pragma unroll
    for (int i = 0; i < 23; i++) lam23 *= LAM;
    const float base = lam23 / 24.0f;
    const float Kc   = MU_ * lam23;

    // Front-batch all 24 loads (fully independent -> MLP = 24)
    float v[T_IN];
    #pragma unroll
    for (int t = 0; t < T_IN; t++)
        v[t] = __ldg(xin + t * IN_T_STRIDE);

    // Bs = window sum; R = truncated EMA Sum_{k<=22} MU*LAM^(22-k) v_k
    float Bs = 0.0f, R = 0.0f;
    #pragma unroll
    for (int t = 0; t < T_IN; t++) {
        Bs += v[t];
        if (t < T_IN - 1) R = fmaf(LAM, R, MU_ * v[t]);   // Horner EMA
    }
    float v23 = v[T_IN - 1];

    float* __restrict__ yout = out + b * OUT_B_STRIDE + mn;

    #pragma unroll
    for (int s = 0; s < T_OUT; s++) {
        const float xo = v[s];                 // element leaving the window
        const float p  = fmaf(base, Bs, R);
        yout[s * MN] = p;
        // Bsum' = Bsum - x_s + p
        Bs = (Bs - xo) + p;
        // R' = LAM*R + MU*v23 - MU*LAM^23 * x_s
        R = fmaf(LAM, R, fmaf(MU_, v23, -Kc * xo));
        v23 = p;
    }
}

extern "C" void kernel_launch(void* const* d_in, const int* in_sizes, int n_in,
                              void* d_out, int out_size)
{
    const float* x = (const float*)d_in[0];
    float* out = (float*)d_out;
    const int total = B * MN;              // 262144 threads
    movavg_kernel<<<total / 256, 256>>>(x, out);
}

// round 4
// speedup vs baseline: 1.0295x; 1.0295x over previous
#include <cuda_runtime.h>
#include <cstdint>

// Problem constants
#define B      32
#define T_IN   24
#define T_OUT  12
#define D      10
#define M      64
#define N      128
#define MN     (M * N)                 // 8192
#define IN_T_STRIDE  (D * MN)          // 81920 floats between t slices
#define IN_B_STRIDE  (T_IN * IN_T_STRIDE)
#define OUT_B_STRIDE (T_OUT * MN)
#define MU_    0.08f
#define LAM    0.92f

#define CHUNK      256                 // mn per CTA
#define NCHUNK     (MN / CHUNK)        // 32
#define THREADS    128                 // 2 series per thread (float2)
#define TILE_BYTES (T_IN * CHUNK * 4)  // 24 KB

struct __align__(128) Smem {
    float tile[T_IN][CHUNK];
    alignas(8) uint64_t mbar;
};

__device__ __forceinline__ uint32_t smem_u32(const void* p) {
    return (uint32_t)__cvta_generic_to_shared(p);
}

__global__ __launch_bounds__(THREADS)
void movavg_kernel(const float* __restrict__ x, float* __restrict__ out)
{
    __shared__ Smem sm;

    const int bid   = blockIdx.x;
    const int b     = bid >> 5;          // / NCHUNK
    const int chunk = bid & (NCHUNK - 1);
    const int tid   = threadIdx.x;

    const uint32_t mb = smem_u32(&sm.mbar);

    if (tid == 0) {
        asm volatile("mbarrier.init.shared::cta.b64 [%0], %1;" :: "r"(mb), "r"(1));
        asm volatile("mbarrier.arrive.expect_tx.shared::cta.b64 _, [%0], %1;"
                     :: "r"(mb), "r"(TILE_BYTES) : "memory");
    }
    __syncthreads();

    // 24 bulk copies of 1 KB each (contiguous per (b,t) slice), issued by 24 threads
    if (tid < T_IN) {
        const float* src = x + (size_t)(b * T_IN + tid) * IN_T_STRIDE + chunk * CHUNK;
        const uint32_t dst = smem_u32(&sm.tile[tid][0]);
        asm volatile(
            "cp.async.bulk.shared::cta.global.mbarrier::complete_tx::bytes "
            "[%0], [%1], %2, [%3];"
            :: "r"(dst), "l"(src), "r"(CHUNK * 4), "r"(mb) : "memory");
    }

    // All threads wait for the full tile
    {
        uint32_t done;
        do {
            asm volatile(
                "{\n\t.reg .pred p;\n\t"
                "mbarrier.try_wait.parity.acquire.cta.shared::cta.b64 p, [%1], %2;\n\t"
                "selp.b32 %0, 1, 0, p;\n\t}"
                : "=r"(done) : "r"(mb), "r"(0) : "memory");
        } while (!done);
    }

    // Compile-time constants
    float lam23 = 1.0f;
    #pragma unroll
    for (int i = 0; i < 23; i++) lam23 *= LAM;
    const float base = lam23 / 24.0f;
    const float Kc   = MU_ * lam23;

    const int ml = tid * 2;   // local mn pair

    // Read the 24-sample window for 2 series from smem (conflict-free)
    float va[T_IN], vb[T_IN];
    #pragma unroll
    for (int t = 0; t < T_IN; t++) {
        const float2 vv = *(const float2*)&sm.tile[t][ml];
        va[t] = vv.x; vb[t] = vv.y;
    }

    // Bs = window sum; R = truncated EMA
    float Bsa = 0.f, Ra = 0.f, Bsb = 0.f, Rb = 0.f;
    #pragma unroll
    for (int t = 0; t < T_IN; t++) {
        Bsa += va[t]; Bsb += vb[t];
        if (t < T_IN - 1) {
            Ra = fmaf(LAM, Ra, MU_ * va[t]);
            Rb = fmaf(LAM, Rb, MU_ * vb[t]);
        }
    }
    float v23a = va[T_IN - 1], v23b = vb[T_IN - 1];

    float* __restrict__ yout = out + (size_t)b * OUT_B_STRIDE + chunk * CHUNK + ml;

    #pragma unroll
    for (int s = 0; s < T_OUT; s++) {
        const float pa = fmaf(base, Bsa, Ra);
        const float pb = fmaf(base, Bsb, Rb);
        float2 o; o.x = pa; o.y = pb;
        *(float2*)(yout + (size_t)s * MN) = o;

        const float xa = va[s], xb = vb[s];
        Bsa = (Bsa - xa) + pa;
        Bsb = (Bsb - xb) + pb;
        Ra = fmaf(LAM, Ra, fmaf(MU_, v23a, -Kc * xa));
        Rb = fmaf(LAM, Rb, fmaf(MU_, v23b, -Kc * xb));
        v23a = pa; v23b = pb;
    }
}

extern "C" void kernel_launch(void* const* d_in, const int* in_sizes, int n_in,
                              void* d_out, int out_size)
{
    const float* x = (const float*)d_in[0];
    float* out = (float*)d_out;
    movavg_kernel<<<B * NCHUNK, THREADS>>>(x, out);   // 1024 CTAs
}